// round 10
// baseline (speedup 1.0000x reference)
#include <cuda_runtime.h>
#include <cuda_fp16.h>
#include <cstdint>

#define B_   8
#define T_   2048
#define D_   256
#define BQ   64
#define BK   32
#define NIT  64         // T_/BK
#define NTHP 256        // pre-kernel threads
#define NTHM 128        // main kernel threads (4 warps) -> 2 CTAs/SM

// ---- f16 hi/lo images: Q pre-scaled by log2(e); K unscaled ----------------
__device__ __align__(16) __half g_qhi[(size_t)B_*T_*D_];
__device__ __align__(16) __half g_qlo[(size_t)B_*T_*D_];
__device__ __align__(16) __half g_khi[(size_t)B_*T_*D_];
__device__ __align__(16) __half g_klo[(size_t)B_*T_*D_];

__device__ __forceinline__ uint32_t h2pack(__half a, __half b){
    return (uint32_t)__half_as_ushort(a) | ((uint32_t)__half_as_ushort(b) << 16);
}
__device__ __forceinline__ float ex2f(float x){
    float r; asm("ex2.approx.f32 %0, %1;" : "=f"(r) : "f"(x)); return r;
}

// one pass over dec (also writes out[...,0:256]) and enc
__global__ void pk_all(const float* __restrict__ dec, const float* __restrict__ enc,
                       float* __restrict__ out){
    size_t g = (size_t)blockIdx.x * NTHP + threadIdx.x;
    const size_t QU = (size_t)B_*T_*D_/4;
    bool isq = (g < QU);
    size_t q = isq ? g : g - QU;
    float4 v = isq ? ((const float4*)dec)[q] : ((const float4*)enc)[q];
    if (isq){   // dec row copy -> out[...,0:256] (unscaled)
        size_t row = q >> 6, c4 = q & 63;
        ((float4*)out)[row*128 + c4] = v;
        const float L2E = 1.4426950408889634f;
        v.x *= L2E; v.y *= L2E; v.z *= L2E; v.w *= L2E;   // log2-domain Q
    }
    __half hx=__float2half_rn(v.x), hy=__float2half_rn(v.y);
    __half hz=__float2half_rn(v.z), hw=__float2half_rn(v.w);
    __half lx=__float2half_rn(v.x-__half2float(hx)), ly=__float2half_rn(v.y-__half2float(hy));
    __half lz=__float2half_rn(v.z-__half2float(hz)), lw=__float2half_rn(v.w-__half2float(hw));
    uint2 hi = make_uint2(h2pack(hx,hy), h2pack(hz,hw));
    uint2 lo = make_uint2(h2pack(lx,ly), h2pack(lz,lw));
    if (isq){ ((uint2*)g_qhi)[q] = hi; ((uint2*)g_qlo)[q] = lo; }
    else    { ((uint2*)g_khi)[q] = hi; ((uint2*)g_klo)[q] = lo; }
}

// ---------------- base-ISA tensor / async primitives ----------------------
__device__ __forceinline__ void ldsm4(uint32_t r[4], uint32_t a){
    asm volatile("ldmatrix.sync.aligned.m8n8.x4.shared.b16 {%0,%1,%2,%3}, [%4];"
        : "=r"(r[0]),"=r"(r[1]),"=r"(r[2]),"=r"(r[3]) : "r"(a));
}
__device__ __forceinline__ void ldsm4t(uint32_t r[4], uint32_t a){
    asm volatile("ldmatrix.sync.aligned.m8n8.x4.trans.shared.b16 {%0,%1,%2,%3}, [%4];"
        : "=r"(r[0]),"=r"(r[1]),"=r"(r[2]),"=r"(r[3]) : "r"(a));
}
__device__ __forceinline__ void mma16816(float d[4], const uint32_t a[4], const uint32_t b[2]){
    asm volatile("mma.sync.aligned.m16n8k16.row.col.f32.f16.f16.f32 "
        "{%0,%1,%2,%3}, {%4,%5,%6,%7}, {%8,%9}, {%0,%1,%2,%3};"
        : "+f"(d[0]),"+f"(d[1]),"+f"(d[2]),"+f"(d[3])
        : "r"(a[0]),"r"(a[1]),"r"(a[2]),"r"(a[3]), "r"(b[0]),"r"(b[1]));
}
__device__ __forceinline__ void cpasync16(uint32_t dst, const void* src){
    uint64_t ga;
    asm volatile("cvta.to.global.u64 %0, %1;" : "=l"(ga) : "l"(src));
    asm volatile("cp.async.cg.shared.global [%0], [%1], 16;" :: "r"(dst), "l"(ga) : "memory");
}
#define CPCOMMIT() asm volatile("cp.async.commit_group;" ::: "memory")
#define CPWAIT0()  asm volatile("cp.async.wait_group 0;" ::: "memory")

// ---- swizzled smem: rows of 512 B; 16B-chunk s at off = r*512 + ((s^(r&7))<<4)
#define SM_QHI  0                    // 64 rows = 32768
#define SM_QLO  32768                // 64 rows = 32768
#define SM_KHI0 65536                // 32 rows = 16384 (stage 0)
#define SM_KHI1 81920                // 32 rows = 16384 (stage 1)
#define SM_KLO  98304                // 32 rows = 16384 (single buffer)
#define SM_TOT  114688               // 112 KB -> 2 CTAs/SM

__global__ __launch_bounds__(NTHM, 2) void attn_main(float* __restrict__ out)
{
    extern __shared__ char smem[];
    const uint32_t smb = (uint32_t)__cvta_generic_to_shared(smem);
    const int tid = threadIdx.x, w = tid >> 5, lane = tid & 31;
    const int qt = blockIdx.x, b = blockIdx.y, t0 = qt * BQ;
    const int g = lane >> 3, lr = lane & 7;

    auto issue_khi = [&](int it){
        uint32_t base = smb + ((it & 1) ? SM_KHI1 : SM_KHI0);
        int e0 = it * BK;
        #pragma unroll
        for (int k = 0; k < 8; k++){
            int i = tid + k * NTHM;              // 0..1023
            int r = i >> 5, s = i & 31;
            uint32_t dst = base + (uint32_t)r*512u + (uint32_t)((s ^ (r & 7)) << 4);
            cpasync16(dst, g_khi + ((size_t)(b*T_ + e0 + r))*D_ + s*8);
        }
        CPCOMMIT();
    };
    auto issue_klo = [&](int it){
        uint32_t base = smb + SM_KLO;
        int e0 = it * BK;
        #pragma unroll
        for (int k = 0; k < 8; k++){
            int i = tid + k * NTHM;
            int r = i >> 5, s = i & 31;
            uint32_t dst = base + (uint32_t)r*512u + (uint32_t)((s ^ (r & 7)) << 4);
            cpasync16(dst, g_klo + ((size_t)(b*T_ + e0 + r))*D_ + s*8);
        }
        CPCOMMIT();
    };

    issue_khi(0);
    issue_klo(0);

    // ---- prologue: Q hi/lo tile -> swizzled smem ---------------------------
    {
        const uint4* qh = (const uint4*)(g_qhi + ((size_t)(b*T_ + t0))*D_);
        const uint4* ql = (const uint4*)(g_qlo + ((size_t)(b*T_ + t0))*D_);
        for (int i = tid; i < BQ*32; i += NTHM){
            int r = i >> 5, s = i & 31;
            uint32_t off = (uint32_t)r*512u + (uint32_t)((s ^ (r & 7)) << 4);
            *(uint4*)(smem + SM_QHI + off) = qh[(size_t)r*32 + s];
            *(uint4*)(smem + SM_QLO + off) = ql[(size_t)r*32 + s];
        }
    }

    const uint32_t qhiR = smb + SM_QHI + (uint32_t)(16*w + (g&1)*8 + lr)*512u;
    const uint32_t qloR = qhiR + (SM_QLO - SM_QHI);
    const uint32_t kr1  = (uint32_t)((g>>1)*8 + lr)*512u;   // GEMM1 B rows (+16/p)
    const uint32_t kr2  = (uint32_t)((g&1)*8 + lr)*512u;    // GEMM2 B rows (+16/kc)

    float mA = -1e30f, mB = -1e30f, psA = 0.f, psB = 0.f;
    float acc[32][4];
    #pragma unroll
    for (int j = 0; j < 32; j++){ acc[j][0]=0.f; acc[j][1]=0.f; acc[j][2]=0.f; acc[j][3]=0.f; }

    #pragma unroll 1
    for (int it = 0; it < NIT; it++){
        CPWAIT0();
        __syncthreads();

        if (it + 1 < NIT) issue_khi(it + 1);

        const uint32_t kb  = smb + ((it & 1) ? SM_KHI1 : SM_KHI0);
        const uint32_t klo = smb + SM_KLO;

        // ---- GEMM1: S[16q x 32e] = Qhi*Khi + Qlo*Khi + Qhi*Klo ------------
        float S[4][4];
        #pragma unroll
        for (int j = 0; j < 4; j++){ S[j][0]=0.f; S[j][1]=0.f; S[j][2]=0.f; S[j][3]=0.f; }

        #pragma unroll
        for (int c = 0; c < 16; c++){
            uint32_t qoff = (uint32_t)((((g>>1) + 2*c) ^ lr) << 4);
            uint32_t ah[4], al[4];
            ldsm4(ah, qhiR + qoff);
            ldsm4(al, qloR + qoff);
            uint32_t koff = (uint32_t)((((g&1) + 2*c) ^ lr) << 4);
            uint32_t bh[2][4], bl[2][4];
            #pragma unroll
            for (int p = 0; p < 2; p++){
                uint32_t rof = kr1 + (uint32_t)p*8192u;
                ldsm4(bh[p], kb  + rof + koff);
                ldsm4(bl[p], klo + rof + koff);
            }
            #pragma unroll
            for (int p = 0; p < 2; p++){ mma16816(S[2*p], ah, bh[p]); mma16816(S[2*p+1], ah, bh[p]+2); }
            #pragma unroll
            for (int p = 0; p < 2; p++){ mma16816(S[2*p], al, bh[p]); mma16816(S[2*p+1], al, bh[p]+2); }
            #pragma unroll
            for (int p = 0; p < 2; p++){ mma16816(S[2*p], ah, bl[p]); mma16816(S[2*p+1], ah, bl[p]+2); }
        }
        __syncthreads();                      // all warps done reading Klo(it)
        if (it + 1 < NIT) issue_klo(it + 1);  // overlaps softmax + GEMM2

        // ---- online softmax in log2 domain (rows rA=16w+(lane>>2), rB=rA+8)
        float bmA = -1e30f, bmB = -1e30f;
        #pragma unroll
        for (int j = 0; j < 4; j++){
            bmA = fmaxf(bmA, fmaxf(S[j][0], S[j][1]));
            bmB = fmaxf(bmB, fmaxf(S[j][2], S[j][3]));
        }
        bmA = fmaxf(bmA, __shfl_xor_sync(0xffffffffu, bmA, 1));
        bmA = fmaxf(bmA, __shfl_xor_sync(0xffffffffu, bmA, 2));
        bmB = fmaxf(bmB, __shfl_xor_sync(0xffffffffu, bmB, 1));
        bmB = fmaxf(bmB, __shfl_xor_sync(0xffffffffu, bmB, 2));

        float mnA = fmaxf(mA, bmA), mnB = fmaxf(mB, bmB);
        float alphaA = ex2f(mA - mnA), alphaB = ex2f(mB - mnB);
        mA = mnA; mB = mnB;

        uint32_t ph[4][2];
        float sA = 0.f, sB = 0.f;
        #pragma unroll
        for (int j = 0; j < 4; j++){
            float p0 = ex2f(S[j][0] - mnA), p1 = ex2f(S[j][1] - mnA);
            float p2 = ex2f(S[j][2] - mnB), p3 = ex2f(S[j][3] - mnB);
            __half2 hA = __floats2half2_rn(p0, p1);
            __half2 hB = __floats2half2_rn(p2, p3);
            float2 fA = __half22float2(hA), fB = __half22float2(hB);
            sA += fA.x + fA.y;  sB += fB.x + fB.y;   // sum exactly what GEMM2 sees
            ph[j][0] = *(uint32_t*)&hA;
            ph[j][1] = *(uint32_t*)&hB;
        }
        psA = psA * alphaA + sA;                      // per-thread partial row sum
        psB = psB * alphaB + sB;                      // (cross-lane reduce in epilogue)

        if (!__all_sync(0xffffffffu, (alphaA == 1.f) & (alphaB == 1.f))){
            #pragma unroll
            for (int j = 0; j < 32; j++){
                acc[j][0] *= alphaA; acc[j][1] *= alphaA;
                acc[j][2] *= alphaB; acc[j][3] *= alphaB;
            }
        }

        // ---- GEMM2: acc[16q x 256d] += P[16q x 32e] * Khi[32e x 256d] -----
        #pragma unroll
        for (int kc = 0; kc < 2; kc++){
            uint32_t a[4] = { ph[2*kc][0], ph[2*kc][1], ph[2*kc+1][0], ph[2*kc+1][1] };
            uint32_t rof = kr2 + (uint32_t)kc*8192u;
            #pragma unroll
            for (int jj = 0; jj < 32; jj += 2){
                uint32_t bb[4];
                ldsm4t(bb, kb + rof + (uint32_t)((((g>>1) + jj) ^ lr) << 4));
                mma16816(acc[jj],   a, bb);
                mma16816(acc[jj+1], a, bb+2);
            }
        }
        // no bottom sync: top-of-next-iter sync protects khi buf reuse
    }

    // ---- epilogue: reduce l across the 4 lanes of each row, write context --
    {
        float lA = psA, lB = psB;
        lA += __shfl_xor_sync(0xffffffffu, lA, 1);
        lA += __shfl_xor_sync(0xffffffffu, lA, 2);
        lB += __shfl_xor_sync(0xffffffffu, lB, 1);
        lB += __shfl_xor_sync(0xffffffffu, lB, 2);
        int rA = 16*w + (lane >> 2);
        float ivA = 1.f / lA, ivB = 1.f / lB;
        float* oA = out + ((size_t)(b*T_ + t0 + rA))    *(size_t)(2*D_) + D_ + (lane&3)*2;
        float* oB = out + ((size_t)(b*T_ + t0 + rA + 8))*(size_t)(2*D_) + D_ + (lane&3)*2;
        #pragma unroll
        for (int j = 0; j < 32; j++){
            *(float2*)(oA + 8*j) = make_float2(acc[j][0]*ivA, acc[j][1]*ivA);
            *(float2*)(oB + 8*j) = make_float2(acc[j][2]*ivB, acc[j][3]*ivB);
        }
    }
}

extern "C" void kernel_launch(void* const* d_in, const int* in_sizes, int n_in,
                              void* d_out, int out_size)
{
    const float* enc = (const float*)d_in[0];  // encoder_outputs [8,2048,256]
    const float* dec = (const float*)d_in[1];  // decoder_outputs [8,2048,256]
    float* out = (float*)d_out;                // [8,2048,512]
    (void)in_sizes; (void)n_in; (void)out_size;

    const int quads2 = 2 * B_*T_*D_/4;         // dec + enc quads
    pk_all<<<quads2/NTHP, NTHP>>>(dec, enc, out);

    cudaFuncSetAttribute(attn_main, cudaFuncAttributeMaxDynamicSharedMemorySize, SM_TOT);
    dim3 grid(T_/BQ, B_);                      // (32, 8) = 256 CTAs, 2 per SM
    attn_main<<<grid, NTHM, SM_TOT>>>(out);
}

// round 11
// speedup vs baseline: 1.2260x; 1.2260x over previous
#include <cuda_runtime.h>
#include <cuda_fp16.h>
#include <cstdint>

#define B_  8
#define T_  2048
#define D_  256
#define BQ  128
#define BK  64
#define NIT 32          // T_/BK
#define NTH 256

// ---- PRE-SWIZZLED f16 hi/lo tile images (exact smem layout, bulk-copyable)
// Q tiles:  [b][qt 0..15]  65536 B each (128 rows x 512 B, chunk s at ((s^(r&7))<<4))
// K tiles:  [b][et 0..31]  32768 B each (64 rows x 512 B)
__device__ __align__(256) unsigned char g_qhi[(size_t)B_*16*65536];
__device__ __align__(256) unsigned char g_qlo[(size_t)B_*16*65536];
__device__ __align__(256) unsigned char g_khi[(size_t)B_*32*32768];
__device__ __align__(256) unsigned char g_klo[(size_t)B_*32*32768];

__device__ __forceinline__ uint32_t h2pack(__half a, __half b){
    return (uint32_t)__half_as_ushort(a) | ((uint32_t)__half_as_ushort(b) << 16);
}

// one pass over dec (also writes out[...,0:256]) and enc; writes swizzled tiles
__global__ void pk_all(const float* __restrict__ dec, const float* __restrict__ enc,
                       float* __restrict__ out){
    size_t g = (size_t)blockIdx.x * NTH + threadIdx.x;
    const size_t QU = (size_t)B_*T_*D_/4;
    bool isq = (g < QU);
    size_t q = isq ? g : g - QU;
    float4 v = isq ? ((const float4*)dec)[q] : ((const float4*)enc)[q];
    if (isq){
        size_t row = q >> 6, c4 = q & 63;
        ((float4*)out)[row*128 + c4] = v;      // dec copy -> out[...,0:256]
    }
    __half hx=__float2half_rn(v.x), hy=__float2half_rn(v.y);
    __half hz=__float2half_rn(v.z), hw=__float2half_rn(v.w);
    __half lx=__float2half_rn(v.x-__half2float(hx)), ly=__float2half_rn(v.y-__half2float(hy));
    __half lz=__float2half_rn(v.z-__half2float(hz)), lw=__float2half_rn(v.w-__half2float(hw));
    uint2 hi = make_uint2(h2pack(hx,hy), h2pack(hz,hw));
    uint2 lo = make_uint2(h2pack(lx,ly), h2pack(lz,lw));

    int c4  = (int)(q & 63);
    int row = (int)(q >> 6);          // global row 0..16383
    int b   = row >> 11, rr = row & 2047;
    uint32_t s = (uint32_t)(c4 >> 1), half8 = (uint32_t)(c4 & 1) * 8u;
    if (isq){
        uint32_t tile = (uint32_t)(rr >> 7), r = (uint32_t)(rr & 127);
        uint32_t off = ((uint32_t)(b*16) + tile)*65536u + r*512u + ((s ^ (r & 7)) << 4) + half8;
        *(uint2*)(g_qhi + off) = hi;
        *(uint2*)(g_qlo + off) = lo;
    } else {
        uint32_t tile = (uint32_t)(rr >> 6), r = (uint32_t)(rr & 63);
        uint32_t off = ((uint32_t)(b*32) + tile)*32768u + r*512u + ((s ^ (r & 7)) << 4) + half8;
        *(uint2*)(g_khi + off) = hi;
        *(uint2*)(g_klo + off) = lo;
    }
}

// ---------------- base-ISA tensor / bulk-async primitives ------------------
__device__ __forceinline__ void ldsm4(uint32_t r[4], uint32_t a){
    asm volatile("ldmatrix.sync.aligned.m8n8.x4.shared.b16 {%0,%1,%2,%3}, [%4];"
        : "=r"(r[0]),"=r"(r[1]),"=r"(r[2]),"=r"(r[3]) : "r"(a));
}
__device__ __forceinline__ void ldsm4t(uint32_t r[4], uint32_t a){
    asm volatile("ldmatrix.sync.aligned.m8n8.x4.trans.shared.b16 {%0,%1,%2,%3}, [%4];"
        : "=r"(r[0]),"=r"(r[1]),"=r"(r[2]),"=r"(r[3]) : "r"(a));
}
__device__ __forceinline__ void mma16816(float d[4], const uint32_t a[4], const uint32_t b[2]){
    asm volatile("mma.sync.aligned.m16n8k16.row.col.f32.f16.f16.f32 "
        "{%0,%1,%2,%3}, {%4,%5,%6,%7}, {%8,%9}, {%0,%1,%2,%3};"
        : "+f"(d[0]),"+f"(d[1]),"+f"(d[2]),"+f"(d[3])
        : "r"(a[0]),"r"(a[1]),"r"(a[2]),"r"(a[3]), "r"(b[0]),"r"(b[1]));
}
__device__ __forceinline__ void bulkcp(uint32_t dst, const void* src, uint32_t bytes, uint32_t mbar){
    uint64_t ga; asm("cvta.to.global.u64 %0, %1;" : "=l"(ga) : "l"(src));
    asm volatile("cp.async.bulk.shared::cta.global.mbarrier::complete_tx::bytes [%0], [%1], %2, [%3];"
        :: "r"(dst), "l"(ga), "r"(bytes), "r"(mbar) : "memory");
}
#define MBI(a,c)   asm volatile("mbarrier.init.shared.b64 [%0], %1;" :: "r"(a), "r"(c) : "memory")
#define MBEX(a,n)  asm volatile("mbarrier.arrive.expect_tx.shared.b64 _, [%0], %1;" :: "r"(a), "r"(n) : "memory")
#define MBARR(a)   asm volatile("mbarrier.arrive.shared.b64 _, [%0];" :: "r"(a) : "memory")
#define MBW(a,ph)  asm volatile("{\n\t.reg .pred P1;\n\tWL_%=:\n\t" \
    "mbarrier.try_wait.parity.acquire.cta.shared::cta.b64 P1, [%0], %1, 0x989680;\n\t" \
    "@P1 bra.uni WD_%=;\n\tbra.uni WL_%=;\n\tWD_%=:\n\t}" :: "r"(a), "r"(ph) : "memory")

// ---- smem layout (identical data layout to R9) ----------------------------
#define SM_QHI  0                    // 128 rows = 65536
#define SM_QLO  65536
#define SM_KHI0 131072               // 64 rows = 32768 (stage 0)
#define SM_KHI1 163840               // stage 1
#define SM_KLO  196608               // single buffer
#define SM_BAR  229376               // 7 mbarriers
#define SM_TOT  229440
// barrier slots
#define MB_FQ   (SM_BAR + 0)
#define MB_FKH0 (SM_BAR + 8)
#define MB_FKH1 (SM_BAR + 16)
#define MB_FKL  (SM_BAR + 24)
#define MB_EKH0 (SM_BAR + 32)
#define MB_EKH1 (SM_BAR + 40)
#define MB_EKL  (SM_BAR + 48)

__global__ __launch_bounds__(NTH) void attn_main(float* __restrict__ out)
{
    extern __shared__ char smem[];
    const uint32_t smb = (uint32_t)__cvta_generic_to_shared(smem);
    const int tid = threadIdx.x, w = tid >> 5, lane = tid & 31;
    const int qt = blockIdx.x, b = blockIdx.y, t0 = qt * BQ;
    const int g = lane >> 3, lr = lane & 7;

    if (tid == 0){
        MBI(smb + MB_FQ,   1); MBI(smb + MB_FKH0, 1); MBI(smb + MB_FKH1, 1);
        MBI(smb + MB_FKL,  1);
        MBI(smb + MB_EKH0, 8); MBI(smb + MB_EKH1, 8); MBI(smb + MB_EKL, 8);
    }
    __syncthreads();

    if (tid == 0){
        // Q tiles (once)
        MBEX(smb + MB_FQ, 131072u);
        bulkcp(smb + SM_QHI, g_qhi + (size_t)(b*16 + qt)*65536u, 65536u, smb + MB_FQ);
        bulkcp(smb + SM_QLO, g_qlo + (size_t)(b*16 + qt)*65536u, 65536u, smb + MB_FQ);
        // K stage 0
        MBEX(smb + MB_FKH0, 32768u);
        bulkcp(smb + SM_KHI0, g_khi + (size_t)(b*32)*32768u, 32768u, smb + MB_FKH0);
        MBEX(smb + MB_FKL, 32768u);
        bulkcp(smb + SM_KLO,  g_klo + (size_t)(b*32)*32768u, 32768u, smb + MB_FKL);
    }

    const uint32_t qhiR = smb + SM_QHI + (uint32_t)(16*w + (g&1)*8 + lr)*512u;
    const uint32_t qloR = qhiR + (SM_QLO - SM_QHI);
    const uint32_t kr1  = (uint32_t)((g>>1)*8 + lr)*512u;   // GEMM1 B rows
    const uint32_t kr2  = (uint32_t)((g&1)*8 + lr)*512u;    // GEMM2 B rows

    float mA = -1e30f, mB = -1e30f, lA = 0.f, lB = 0.f;
    float acc[32][4];
    #pragma unroll
    for (int j = 0; j < 32; j++){ acc[j][0]=0.f; acc[j][1]=0.f; acc[j][2]=0.f; acc[j][3]=0.f; }

    MBW(smb + MB_FQ, 0);    // Q resident

    #pragma unroll 1
    for (int it = 0; it < NIT; it++){
        // producer: issue khi(it+1) into the other stage
        if (tid == 0 && it + 1 < NIT){
            int n = it + 1;
            uint32_t fb = (n & 1) ? (smb + MB_FKH1) : (smb + MB_FKH0);
            uint32_t eb = (n & 1) ? (smb + MB_EKH1) : (smb + MB_EKH0);
            if (n >= 2) MBW(eb, ((n - 2) >> 1) & 1);
            MBEX(fb, 32768u);
            bulkcp(smb + ((n & 1) ? SM_KHI1 : SM_KHI0),
                   g_khi + (size_t)(b*32 + n)*32768u, 32768u, fb);
        }
        // consume khi(it) + klo(it)
        MBW(smb + ((it & 1) ? MB_FKH1 : MB_FKH0), (it >> 1) & 1);
        MBW(smb + MB_FKL, it & 1);

        const uint32_t kb  = smb + ((it & 1) ? SM_KHI1 : SM_KHI0);
        const uint32_t klo = smb + SM_KLO;

        // ---- GEMM1: S[16q x 64e] = Qhi*Khi + Qlo*Khi + Qhi*Klo ------------
        float S[8][4];
        #pragma unroll
        for (int j = 0; j < 8; j++){ S[j][0]=0.f; S[j][1]=0.f; S[j][2]=0.f; S[j][3]=0.f; }

        #pragma unroll
        for (int c = 0; c < 16; c++){
            uint32_t qoff = (uint32_t)((((g>>1) + 2*c) ^ lr) << 4);
            uint32_t ah[4], al[4];
            ldsm4(ah, qhiR + qoff);
            ldsm4(al, qloR + qoff);
            uint32_t koff = (uint32_t)((((g&1) + 2*c) ^ lr) << 4);
            uint32_t bh[4][4], bl[4][4];
            #pragma unroll
            for (int p = 0; p < 4; p++){
                uint32_t rof = kr1 + (uint32_t)p*8192u;
                ldsm4(bh[p], kb  + rof + koff);
                ldsm4(bl[p], klo + rof + koff);
            }
            #pragma unroll
            for (int p = 0; p < 4; p++){ mma16816(S[2*p], ah, bh[p]); mma16816(S[2*p+1], ah, bh[p]+2); }
            #pragma unroll
            for (int p = 0; p < 4; p++){ mma16816(S[2*p], al, bh[p]); mma16816(S[2*p+1], al, bh[p]+2); }
            #pragma unroll
            for (int p = 0; p < 4; p++){ mma16816(S[2*p], ah, bl[p]); mma16816(S[2*p+1], ah, bl[p]+2); }
        }
        if (lane == 0) MBARR(smb + MB_EKL);   // this warp done reading Klo(it)

        // ---- online softmax (rows rA=16w+(lane>>2), rB=rA+8) --------------
        float bmA = -1e30f, bmB = -1e30f;
        #pragma unroll
        for (int j = 0; j < 8; j++){
            bmA = fmaxf(bmA, fmaxf(S[j][0], S[j][1]));
            bmB = fmaxf(bmB, fmaxf(S[j][2], S[j][3]));
        }
        bmA = fmaxf(bmA, __shfl_xor_sync(0xffffffffu, bmA, 1));
        bmA = fmaxf(bmA, __shfl_xor_sync(0xffffffffu, bmA, 2));
        bmB = fmaxf(bmB, __shfl_xor_sync(0xffffffffu, bmB, 1));
        bmB = fmaxf(bmB, __shfl_xor_sync(0xffffffffu, bmB, 2));

        float mnA = fmaxf(mA, bmA), mnB = fmaxf(mB, bmB);
        float alphaA = __expf(mA - mnA), alphaB = __expf(mB - mnB);
        mA = mnA; mB = mnB;

        uint32_t ph[8][2];
        float sA = 0.f, sB = 0.f;
        #pragma unroll
        for (int j = 0; j < 8; j++){
            float p0 = __expf(S[j][0] - mnA), p1 = __expf(S[j][1] - mnA);
            float p2 = __expf(S[j][2] - mnB), p3 = __expf(S[j][3] - mnB);
            __half2 hA = __floats2half2_rn(p0, p1);
            __half2 hB = __floats2half2_rn(p2, p3);
            float2 fA = __half22float2(hA), fB = __half22float2(hB);
            sA += fA.x + fA.y;  sB += fB.x + fB.y;   // sum exactly what GEMM2 sees
            ph[j][0] = *(uint32_t*)&hA;
            ph[j][1] = *(uint32_t*)&hB;
        }
        sA += __shfl_xor_sync(0xffffffffu, sA, 1);
        sA += __shfl_xor_sync(0xffffffffu, sA, 2);
        sB += __shfl_xor_sync(0xffffffffu, sB, 1);
        sB += __shfl_xor_sync(0xffffffffu, sB, 2);
        lA = lA * alphaA + sA;
        lB = lB * alphaB + sB;

        if (!__all_sync(0xffffffffu, (alphaA == 1.f) & (alphaB == 1.f))){
            #pragma unroll
            for (int j = 0; j < 32; j++){
                acc[j][0] *= alphaA; acc[j][1] *= alphaA;
                acc[j][2] *= alphaB; acc[j][3] *= alphaB;
            }
        }

        // producer: klo(it+1) once all warps released Klo(it)
        if (tid == 0 && it + 1 < NIT){
            MBW(smb + MB_EKL, it & 1);
            MBEX(smb + MB_FKL, 32768u);
            bulkcp(smb + SM_KLO, g_klo + (size_t)(b*32 + it + 1)*32768u, 32768u, smb + MB_FKL);
        }

        // ---- GEMM2: acc[16q x 256d] += P[16q x 64e] * Khi[64e x 256d] -----
        #pragma unroll
        for (int kc = 0; kc < 4; kc++){
            uint32_t a[4] = { ph[2*kc][0], ph[2*kc][1], ph[2*kc+1][0], ph[2*kc+1][1] };
            uint32_t rof = kr2 + (uint32_t)kc*8192u;
            #pragma unroll
            for (int jj = 0; jj < 32; jj += 2){
                uint32_t bb[4];
                ldsm4t(bb, kb + rof + (uint32_t)((((g>>1) + jj) ^ lr) << 4));
                mma16816(acc[jj],   a, bb);
                mma16816(acc[jj+1], a, bb+2);
            }
        }
        if (lane == 0) MBARR(smb + ((it & 1) ? MB_EKH1 : MB_EKH0));  // done with Khi(it)
    }

    // ---- epilogue: out[.., 256:512] = acc / l (dec half written by pk_all)
    {
        int rA = 16*w + (lane >> 2);
        float ivA = 1.f / lA, ivB = 1.f / lB;
        float* oA = out + ((size_t)(b*T_ + t0 + rA))    *(size_t)(2*D_) + D_ + (lane&3)*2;
        float* oB = out + ((size_t)(b*T_ + t0 + rA + 8))*(size_t)(2*D_) + D_ + (lane&3)*2;
        #pragma unroll
        for (int j = 0; j < 32; j++){
            *(float2*)(oA + 8*j) = make_float2(acc[j][0]*ivA, acc[j][1]*ivA);
            *(float2*)(oB + 8*j) = make_float2(acc[j][2]*ivB, acc[j][3]*ivB);
        }
    }
}

extern "C" void kernel_launch(void* const* d_in, const int* in_sizes, int n_in,
                              void* d_out, int out_size)
{
    const float* enc = (const float*)d_in[0];  // encoder_outputs [8,2048,256]
    const float* dec = (const float*)d_in[1];  // decoder_outputs [8,2048,256]
    float* out = (float*)d_out;                // [8,2048,512]
    (void)in_sizes; (void)n_in; (void)out_size;

    const int quads2 = 2 * B_*T_*D_/4;         // dec + enc quads
    pk_all<<<quads2/NTH, NTH>>>(dec, enc, out);

    cudaFuncSetAttribute(attn_main, cudaFuncAttributeMaxDynamicSharedMemorySize, SM_TOT);
    dim3 grid(T_/BQ, B_);                      // (16, 8) = 128 CTAs, single wave
    attn_main<<<grid, NTH, SM_TOT>>>(out);
}

// round 12
// speedup vs baseline: 1.2665x; 1.0331x over previous
#include <cuda_runtime.h>
#include <cuda_fp16.h>
#include <cstdint>

#define B_  8
#define T_  2048
#define D_  256
#define BQ  128
#define BK  64
#define NIT 32          // T_/BK
#define NTH 256

// ---- PRE-SWIZZLED f16 hi/lo tile images (exact smem layout, bulk-copyable)
// Q tiles:  [b][qt 0..15]  65536 B each (128 rows x 512 B, chunk s at ((s^(r&7))<<4))
// K tiles:  [b][et 0..31]  32768 B each (64 rows x 512 B)
// Q is pre-scaled by log2(e)  ->  S arrives in log2 domain, softmax uses raw ex2.
__device__ __align__(256) unsigned char g_qhi[(size_t)B_*16*65536];
__device__ __align__(256) unsigned char g_qlo[(size_t)B_*16*65536];
__device__ __align__(256) unsigned char g_khi[(size_t)B_*32*32768];
__device__ __align__(256) unsigned char g_klo[(size_t)B_*32*32768];

__device__ __forceinline__ uint32_t h2pack(__half a, __half b){
    return (uint32_t)__half_as_ushort(a) | ((uint32_t)__half_as_ushort(b) << 16);
}
__device__ __forceinline__ float ex2f(float x){
    float r; asm("ex2.approx.f32 %0, %1;" : "=f"(r) : "f"(x)); return r;
}
__device__ __forceinline__ uint32_t h2ex2(uint32_t x){    // ex2 on packed half2
    uint32_t r; asm("ex2.approx.f16x2 %0, %1;" : "=r"(r) : "r"(x)); return r;
}

// one pass over dec (also writes out[...,0:256]) and enc; writes swizzled tiles
__global__ void pk_all(const float* __restrict__ dec, const float* __restrict__ enc,
                       float* __restrict__ out){
    size_t g = (size_t)blockIdx.x * NTH + threadIdx.x;
    const size_t QU = (size_t)B_*T_*D_/4;
    bool isq = (g < QU);
    size_t q = isq ? g : g - QU;
    float4 v = isq ? ((const float4*)dec)[q] : ((const float4*)enc)[q];
    if (isq){
        size_t row = q >> 6, c4 = q & 63;
        ((float4*)out)[row*128 + c4] = v;      // dec copy -> out[...,0:256]
        const float L2E = 1.4426950408889634f; // Q in log2 domain
        v.x *= L2E; v.y *= L2E; v.z *= L2E; v.w *= L2E;
    }
    __half hx=__float2half_rn(v.x), hy=__float2half_rn(v.y);
    __half hz=__float2half_rn(v.z), hw=__float2half_rn(v.w);
    __half lx=__float2half_rn(v.x-__half2float(hx)), ly=__float2half_rn(v.y-__half2float(hy));
    __half lz=__float2half_rn(v.z-__half2float(hz)), lw=__float2half_rn(v.w-__half2float(hw));
    uint2 hi = make_uint2(h2pack(hx,hy), h2pack(hz,hw));
    uint2 lo = make_uint2(h2pack(lx,ly), h2pack(lz,lw));

    int c4  = (int)(q & 63);
    int row = (int)(q >> 6);          // global row 0..16383
    int b   = row >> 11, rr = row & 2047;
    uint32_t s = (uint32_t)(c4 >> 1), half8 = (uint32_t)(c4 & 1) * 8u;
    if (isq){
        uint32_t tile = (uint32_t)(rr >> 7), r = (uint32_t)(rr & 127);
        uint32_t off = ((uint32_t)(b*16) + tile)*65536u + r*512u + ((s ^ (r & 7)) << 4) + half8;
        *(uint2*)(g_qhi + off) = hi;
        *(uint2*)(g_qlo + off) = lo;
    } else {
        uint32_t tile = (uint32_t)(rr >> 6), r = (uint32_t)(rr & 63);
        uint32_t off = ((uint32_t)(b*32) + tile)*32768u + r*512u + ((s ^ (r & 7)) << 4) + half8;
        *(uint2*)(g_khi + off) = hi;
        *(uint2*)(g_klo + off) = lo;
    }
}

// ---------------- base-ISA tensor / bulk-async primitives ------------------
__device__ __forceinline__ void ldsm4(uint32_t r[4], uint32_t a){
    asm volatile("ldmatrix.sync.aligned.m8n8.x4.shared.b16 {%0,%1,%2,%3}, [%4];"
        : "=r"(r[0]),"=r"(r[1]),"=r"(r[2]),"=r"(r[3]) : "r"(a));
}
__device__ __forceinline__ void ldsm4t(uint32_t r[4], uint32_t a){
    asm volatile("ldmatrix.sync.aligned.m8n8.x4.trans.shared.b16 {%0,%1,%2,%3}, [%4];"
        : "=r"(r[0]),"=r"(r[1]),"=r"(r[2]),"=r"(r[3]) : "r"(a));
}
__device__ __forceinline__ void mma16816(float d[4], const uint32_t a[4], const uint32_t b[2]){
    asm volatile("mma.sync.aligned.m16n8k16.row.col.f32.f16.f16.f32 "
        "{%0,%1,%2,%3}, {%4,%5,%6,%7}, {%8,%9}, {%0,%1,%2,%3};"
        : "+f"(d[0]),"+f"(d[1]),"+f"(d[2]),"+f"(d[3])
        : "r"(a[0]),"r"(a[1]),"r"(a[2]),"r"(a[3]), "r"(b[0]),"r"(b[1]));
}
__device__ __forceinline__ void bulkcp(uint32_t dst, const void* src, uint32_t bytes, uint32_t mbar){
    uint64_t ga; asm("cvta.to.global.u64 %0, %1;" : "=l"(ga) : "l"(src));
    asm volatile("cp.async.bulk.shared::cta.global.mbarrier::complete_tx::bytes [%0], [%1], %2, [%3];"
        :: "r"(dst), "l"(ga), "r"(bytes), "r"(mbar) : "memory");
}
#define MBI(a,c)   asm volatile("mbarrier.init.shared.b64 [%0], %1;" :: "r"(a), "r"(c) : "memory")
#define MBEX(a,n)  asm volatile("mbarrier.arrive.expect_tx.shared.b64 _, [%0], %1;" :: "r"(a), "r"(n) : "memory")
#define MBARR(a)   asm volatile("mbarrier.arrive.shared.b64 _, [%0];" :: "r"(a) : "memory")
#define MBW(a,ph)  asm volatile("{\n\t.reg .pred P1;\n\tWL_%=:\n\t" \
    "mbarrier.try_wait.parity.acquire.cta.shared::cta.b64 P1, [%0], %1, 0x989680;\n\t" \
    "@P1 bra.uni WD_%=;\n\tbra.uni WL_%=;\n\tWD_%=:\n\t}" :: "r"(a), "r"(ph) : "memory")

// ---- smem layout -----------------------------------------------------------
#define SM_QHI  0                    // 128 rows = 65536
#define SM_QLO  65536
#define SM_KHI0 131072               // 64 rows = 32768 (stage 0)
#define SM_KHI1 163840               // stage 1
#define SM_KLO  196608               // single buffer
#define SM_BAR  229376               // 7 mbarriers
#define SM_TOT  229440
#define MB_FQ   (SM_BAR + 0)
#define MB_FKH0 (SM_BAR + 8)
#define MB_FKH1 (SM_BAR + 16)
#define MB_FKL  (SM_BAR + 24)
#define MB_EKH0 (SM_BAR + 32)
#define MB_EKH1 (SM_BAR + 40)
#define MB_EKL  (SM_BAR + 48)

__global__ __launch_bounds__(NTH) void attn_main(float* __restrict__ out)
{
    extern __shared__ char smem[];
    const uint32_t smb = (uint32_t)__cvta_generic_to_shared(smem);
    const int tid = threadIdx.x, w = tid >> 5, lane = tid & 31;
    const int qt = blockIdx.x, b = blockIdx.y, t0 = qt * BQ;
    const int g = lane >> 3, lr = lane & 7;

    if (tid == 0){
        MBI(smb + MB_FQ,   1); MBI(smb + MB_FKH0, 1); MBI(smb + MB_FKH1, 1);
        MBI(smb + MB_FKL,  1);
        MBI(smb + MB_EKH0, 8); MBI(smb + MB_EKH1, 8); MBI(smb + MB_EKL, 8);
    }
    __syncthreads();

    if (tid == 0){
        MBEX(smb + MB_FQ, 131072u);
        bulkcp(smb + SM_QHI, g_qhi + (size_t)(b*16 + qt)*65536u, 65536u, smb + MB_FQ);
        bulkcp(smb + SM_QLO, g_qlo + (size_t)(b*16 + qt)*65536u, 65536u, smb + MB_FQ);
        MBEX(smb + MB_FKH0, 32768u);
        bulkcp(smb + SM_KHI0, g_khi + (size_t)(b*32)*32768u, 32768u, smb + MB_FKH0);
        MBEX(smb + MB_FKL, 32768u);
        bulkcp(smb + SM_KLO,  g_klo + (size_t)(b*32)*32768u, 32768u, smb + MB_FKL);
    }

    const uint32_t qhiR = smb + SM_QHI + (uint32_t)(16*w + (g&1)*8 + lr)*512u;
    const uint32_t qloR = qhiR + (SM_QLO - SM_QHI);
    const uint32_t kr1  = (uint32_t)((g>>1)*8 + lr)*512u;   // GEMM1 B rows
    const uint32_t kr2  = (uint32_t)((g&1)*8 + lr)*512u;    // GEMM2 B rows

    float mA = -1e30f, mB = -1e30f, psA = 0.f, psB = 0.f;
    float acc[32][4];
    #pragma unroll
    for (int j = 0; j < 32; j++){ acc[j][0]=0.f; acc[j][1]=0.f; acc[j][2]=0.f; acc[j][3]=0.f; }

    MBW(smb + MB_FQ, 0);    // Q resident

    #pragma unroll 1
    for (int it = 0; it < NIT; it++){
        if (tid == 0 && it + 1 < NIT){
            int n = it + 1;
            uint32_t fb = (n & 1) ? (smb + MB_FKH1) : (smb + MB_FKH0);
            uint32_t eb = (n & 1) ? (smb + MB_EKH1) : (smb + MB_EKH0);
            if (n >= 2) MBW(eb, ((n - 2) >> 1) & 1);
            MBEX(fb, 32768u);
            bulkcp(smb + ((n & 1) ? SM_KHI1 : SM_KHI0),
                   g_khi + (size_t)(b*32 + n)*32768u, 32768u, fb);
        }
        MBW(smb + ((it & 1) ? MB_FKH1 : MB_FKH0), (it >> 1) & 1);
        MBW(smb + MB_FKL, it & 1);

        const uint32_t kb  = smb + ((it & 1) ? SM_KHI1 : SM_KHI0);
        const uint32_t klo = smb + SM_KLO;

        // ---- GEMM1: S[16q x 64e] = Qhi*Khi + Qlo*Khi + Qhi*Klo (log2 dom) -
        float S[8][4];
        #pragma unroll
        for (int j = 0; j < 8; j++){ S[j][0]=0.f; S[j][1]=0.f; S[j][2]=0.f; S[j][3]=0.f; }

        #pragma unroll
        for (int c = 0; c < 16; c++){
            uint32_t qoff = (uint32_t)((((g>>1) + 2*c) ^ lr) << 4);
            uint32_t ah[4], al[4];
            ldsm4(ah, qhiR + qoff);
            ldsm4(al, qloR + qoff);
            uint32_t koff = (uint32_t)((((g&1) + 2*c) ^ lr) << 4);
            uint32_t bh[4][4], bl[4][4];
            #pragma unroll
            for (int p = 0; p < 4; p++){
                uint32_t rof = kr1 + (uint32_t)p*8192u;
                ldsm4(bh[p], kb  + rof + koff);
                ldsm4(bl[p], klo + rof + koff);
            }
            #pragma unroll
            for (int p = 0; p < 4; p++){ mma16816(S[2*p], ah, bh[p]); mma16816(S[2*p+1], ah, bh[p]+2); }
            #pragma unroll
            for (int p = 0; p < 4; p++){ mma16816(S[2*p], al, bh[p]); mma16816(S[2*p+1], al, bh[p]+2); }
            #pragma unroll
            for (int p = 0; p < 4; p++){ mma16816(S[2*p], ah, bl[p]); mma16816(S[2*p+1], ah, bl[p]+2); }
        }
        if (lane == 0) MBARR(smb + MB_EKL);   // this warp done reading Klo(it)

        // ---- online softmax, log2 domain (rows rA=16w+(lane>>2), rB=rA+8) -
        float bmA = -1e30f, bmB = -1e30f;
        #pragma unroll
        for (int j = 0; j < 8; j++){
            bmA = fmaxf(bmA, fmaxf(S[j][0], S[j][1]));
            bmB = fmaxf(bmB, fmaxf(S[j][2], S[j][3]));
        }
        bmA = fmaxf(bmA, __shfl_xor_sync(0xffffffffu, bmA, 1));
        bmA = fmaxf(bmA, __shfl_xor_sync(0xffffffffu, bmA, 2));
        bmB = fmaxf(bmB, __shfl_xor_sync(0xffffffffu, bmB, 1));
        bmB = fmaxf(bmB, __shfl_xor_sync(0xffffffffu, bmB, 2));

        float mnA = fmaxf(mA, bmA), mnB = fmaxf(mB, bmB);
        float alphaA = ex2f(mA - mnA), alphaB = ex2f(mB - mnB);
        mA = mnA; mB = mnB;

        uint32_t ph[8][2];
        float sA = 0.f, sB = 0.f;
        #pragma unroll
        for (int j = 0; j < 8; j++){
            __half2 dA = __floats2half2_rn(S[j][0] - mnA, S[j][1] - mnA);
            __half2 dB = __floats2half2_rn(S[j][2] - mnB, S[j][3] - mnB);
            uint32_t pA = h2ex2(*(uint32_t*)&dA);       // packed f16 P, 1 MUFU / 2 vals
            uint32_t pB = h2ex2(*(uint32_t*)&dB);
            float2 fA = __half22float2(*(__half2*)&pA);
            float2 fB = __half22float2(*(__half2*)&pB);
            sA += fA.x + fA.y;  sB += fB.x + fB.y;      // sum exactly what GEMM2 sees
            ph[j][0] = pA;
            ph[j][1] = pB;
        }
        psA = psA * alphaA + sA;      // per-thread partial row sums;
        psB = psB * alphaB + sB;      // cross-lane reduce deferred to epilogue

        if (!__all_sync(0xffffffffu, (alphaA == 1.f) & (alphaB == 1.f))){
            #pragma unroll
            for (int j = 0; j < 32; j++){
                acc[j][0] *= alphaA; acc[j][1] *= alphaA;
                acc[j][2] *= alphaB; acc[j][3] *= alphaB;
            }
        }

        // producer: klo(it+1) once all warps released Klo(it)
        if (tid == 0 && it + 1 < NIT){
            MBW(smb + MB_EKL, it & 1);
            MBEX(smb + MB_FKL, 32768u);
            bulkcp(smb + SM_KLO, g_klo + (size_t)(b*32 + it + 1)*32768u, 32768u, smb + MB_FKL);
        }

        // ---- GEMM2: acc[16q x 256d] += P[16q x 64e] * Khi[64e x 256d] -----
        #pragma unroll
        for (int kc = 0; kc < 4; kc++){
            uint32_t a[4] = { ph[2*kc][0], ph[2*kc][1], ph[2*kc+1][0], ph[2*kc+1][1] };
            uint32_t rof = kr2 + (uint32_t)kc*8192u;
            #pragma unroll
            for (int jj = 0; jj < 32; jj += 2){
                uint32_t bb[4];
                ldsm4t(bb, kb + rof + (uint32_t)((((g>>1) + jj) ^ lr) << 4));
                mma16816(acc[jj],   a, bb);
                mma16816(acc[jj+1], a, bb+2);
            }
        }
        if (lane == 0) MBARR(smb + ((it & 1) ? MB_EKH1 : MB_EKH0));  // done with Khi(it)
    }

    // ---- epilogue: reduce l across the 4 lanes of each row, write context --
    {
        float lA = psA, lB = psB;
        lA += __shfl_xor_sync(0xffffffffu, lA, 1);
        lA += __shfl_xor_sync(0xffffffffu, lA, 2);
        lB += __shfl_xor_sync(0xffffffffu, lB, 1);
        lB += __shfl_xor_sync(0xffffffffu, lB, 2);
        int rA = 16*w + (lane >> 2);
        float ivA = 1.f / lA, ivB = 1.f / lB;
        float* oA = out + ((size_t)(b*T_ + t0 + rA))    *(size_t)(2*D_) + D_ + (lane&3)*2;
        float* oB = out + ((size_t)(b*T_ + t0 + rA + 8))*(size_t)(2*D_) + D_ + (lane&3)*2;
        #pragma unroll
        for (int j = 0; j < 32; j++){
            *(float2*)(oA + 8*j) = make_float2(acc[j][0]*ivA, acc[j][1]*ivA);
            *(float2*)(oB + 8*j) = make_float2(acc[j][2]*ivB, acc[j][3]*ivB);
        }
    }
}

extern "C" void kernel_launch(void* const* d_in, const int* in_sizes, int n_in,
                              void* d_out, int out_size)
{
    const float* enc = (const float*)d_in[0];  // encoder_outputs [8,2048,256]
    const float* dec = (const float*)d_in[1];  // decoder_outputs [8,2048,256]
    float* out = (float*)d_out;                // [8,2048,512]
    (void)in_sizes; (void)n_in; (void)out_size;

    const int quads2 = 2 * B_*T_*D_/4;         // dec + enc quads
    pk_all<<<quads2/NTH, NTH>>>(dec, enc, out);

    cudaFuncSetAttribute(attn_main, cudaFuncAttributeMaxDynamicSharedMemorySize, SM_TOT);
    dim3 grid(T_/BQ, B_);                      // (16, 8) = 128 CTAs, single wave
    attn_main<<<grid, NTH, SM_TOT>>>(out);
}

// round 13
// speedup vs baseline: 1.6244x; 1.2826x over previous
#include <cuda_runtime.h>
#include <cuda_fp16.h>
#include <cstdint>

#define B_  8
#define T_  2048
#define D_  256
#define BQ  128
#define BK  64
#define NIT 32          // T_/BK
#define NTH 256

// ---- PRE-SWIZZLED f16 tile images (exact smem layout, bulk-copyable)
// Q tiles:  [b][qt 0..15]  65536 B each (128 rows x 512 B, chunk s at ((s^(r&7))<<4))
// K tiles:  [b][et 0..31]  32768 B each (64 rows x 512 B)
// Q is pre-scaled by log2(e); Q keeps an f16 lo-image (2-chain split), K is hi-only.
__device__ __align__(256) unsigned char g_qhi[(size_t)B_*16*65536];
__device__ __align__(256) unsigned char g_qlo[(size_t)B_*16*65536];
__device__ __align__(256) unsigned char g_khi[(size_t)B_*32*32768];

__device__ __forceinline__ uint32_t h2pack(__half a, __half b){
    return (uint32_t)__half_as_ushort(a) | ((uint32_t)__half_as_ushort(b) << 16);
}
__device__ __forceinline__ float ex2f(float x){
    float r; asm("ex2.approx.f32 %0, %1;" : "=f"(r) : "f"(x)); return r;
}
__device__ __forceinline__ uint32_t h2ex2(uint32_t x){    // ex2 on packed half2
    uint32_t r; asm("ex2.approx.f16x2 %0, %1;" : "=r"(r) : "r"(x)); return r;
}

// one pass over dec (also writes out[...,0:256]) and enc; writes swizzled tiles
__global__ void pk_all(const float* __restrict__ dec, const float* __restrict__ enc,
                       float* __restrict__ out){
    size_t g = (size_t)blockIdx.x * NTH + threadIdx.x;
    const size_t QU = (size_t)B_*T_*D_/4;
    bool isq = (g < QU);
    size_t q = isq ? g : g - QU;
    float4 v = isq ? ((const float4*)dec)[q] : ((const float4*)enc)[q];
    if (isq){
        size_t row = q >> 6, c4 = q & 63;
        ((float4*)out)[row*128 + c4] = v;      // dec copy -> out[...,0:256]
        const float L2E = 1.4426950408889634f; // Q in log2 domain
        v.x *= L2E; v.y *= L2E; v.z *= L2E; v.w *= L2E;
    }
    __half hx=__float2half_rn(v.x), hy=__float2half_rn(v.y);
    __half hz=__float2half_rn(v.z), hw=__float2half_rn(v.w);
    uint2 hi = make_uint2(h2pack(hx,hy), h2pack(hz,hw));

    int c4  = (int)(q & 63);
    int row = (int)(q >> 6);          // global row 0..16383
    int b   = row >> 11, rr = row & 2047;
    uint32_t s = (uint32_t)(c4 >> 1), half8 = (uint32_t)(c4 & 1) * 8u;
    if (isq){
        __half lx=__float2half_rn(v.x-__half2float(hx)), ly=__float2half_rn(v.y-__half2float(hy));
        __half lz=__float2half_rn(v.z-__half2float(hz)), lw=__float2half_rn(v.w-__half2float(hw));
        uint2 lo = make_uint2(h2pack(lx,ly), h2pack(lz,lw));
        uint32_t tile = (uint32_t)(rr >> 7), r = (uint32_t)(rr & 127);
        uint32_t off = ((uint32_t)(b*16) + tile)*65536u + r*512u + ((s ^ (r & 7)) << 4) + half8;
        *(uint2*)(g_qhi + off) = hi;
        *(uint2*)(g_qlo + off) = lo;
    } else {
        uint32_t tile = (uint32_t)(rr >> 6), r = (uint32_t)(rr & 63);
        uint32_t off = ((uint32_t)(b*32) + tile)*32768u + r*512u + ((s ^ (r & 7)) << 4) + half8;
        *(uint2*)(g_khi + off) = hi;
    }
}

// ---------------- base-ISA tensor / bulk-async primitives ------------------
__device__ __forceinline__ void ldsm4(uint32_t r[4], uint32_t a){
    asm volatile("ldmatrix.sync.aligned.m8n8.x4.shared.b16 {%0,%1,%2,%3}, [%4];"
        : "=r"(r[0]),"=r"(r[1]),"=r"(r[2]),"=r"(r[3]) : "r"(a));
}
__device__ __forceinline__ void ldsm4t(uint32_t r[4], uint32_t a){
    asm volatile("ldmatrix.sync.aligned.m8n8.x4.trans.shared.b16 {%0,%1,%2,%3}, [%4];"
        : "=r"(r[0]),"=r"(r[1]),"=r"(r[2]),"=r"(r[3]) : "r"(a));
}
__device__ __forceinline__ void mma16816(float d[4], const uint32_t a[4], const uint32_t b[2]){
    asm volatile("mma.sync.aligned.m16n8k16.row.col.f32.f16.f16.f32 "
        "{%0,%1,%2,%3}, {%4,%5,%6,%7}, {%8,%9}, {%0,%1,%2,%3};"
        : "+f"(d[0]),"+f"(d[1]),"+f"(d[2]),"+f"(d[3])
        : "r"(a[0]),"r"(a[1]),"r"(a[2]),"r"(a[3]), "r"(b[0]),"r"(b[1]));
}
__device__ __forceinline__ void bulkcp(uint32_t dst, const void* src, uint32_t bytes, uint32_t mbar){
    uint64_t ga; asm("cvta.to.global.u64 %0, %1;" : "=l"(ga) : "l"(src));
    asm volatile("cp.async.bulk.shared::cta.global.mbarrier::complete_tx::bytes [%0], [%1], %2, [%3];"
        :: "r"(dst), "l"(ga), "r"(bytes), "r"(mbar) : "memory");
}
#define MBI(a,c)   asm volatile("mbarrier.init.shared.b64 [%0], %1;" :: "r"(a), "r"(c) : "memory")
#define MBEX(a,n)  asm volatile("mbarrier.arrive.expect_tx.shared.b64 _, [%0], %1;" :: "r"(a), "r"(n) : "memory")
#define MBARR(a)   asm volatile("mbarrier.arrive.shared.b64 _, [%0];" :: "r"(a) : "memory")
#define MBW(a,ph)  asm volatile("{\n\t.reg .pred P1;\n\tWL_%=:\n\t" \
    "mbarrier.try_wait.parity.acquire.cta.shared::cta.b64 P1, [%0], %1, 0x989680;\n\t" \
    "@P1 bra.uni WD_%=;\n\tbra.uni WL_%=;\n\tWD_%=:\n\t}" :: "r"(a), "r"(ph) : "memory")

// ---- smem layout -----------------------------------------------------------
#define SM_QHI  0                    // 128 rows = 65536
#define SM_QLO  65536
#define SM_KHI0 131072               // 64 rows = 32768 (stage 0)
#define SM_KHI1 163840               // stage 1
#define SM_BAR  196608               // 5 mbarriers
#define SM_TOT  196672
#define MB_FQ   (SM_BAR + 0)
#define MB_FKH0 (SM_BAR + 8)
#define MB_FKH1 (SM_BAR + 16)
#define MB_EKH0 (SM_BAR + 24)
#define MB_EKH1 (SM_BAR + 32)

__global__ __launch_bounds__(NTH) void attn_main(float* __restrict__ out)
{
    extern __shared__ char smem[];
    const uint32_t smb = (uint32_t)__cvta_generic_to_shared(smem);
    const int tid = threadIdx.x, w = tid >> 5, lane = tid & 31;
    const int qt = blockIdx.x, b = blockIdx.y, t0 = qt * BQ;
    const int g = lane >> 3, lr = lane & 7;

    if (tid == 0){
        MBI(smb + MB_FQ,   1); MBI(smb + MB_FKH0, 1); MBI(smb + MB_FKH1, 1);
        MBI(smb + MB_EKH0, 8); MBI(smb + MB_EKH1, 8);
    }
    __syncthreads();

    if (tid == 0){
        MBEX(smb + MB_FQ, 131072u);
        bulkcp(smb + SM_QHI, g_qhi + (size_t)(b*16 + qt)*65536u, 65536u, smb + MB_FQ);
        bulkcp(smb + SM_QLO, g_qlo + (size_t)(b*16 + qt)*65536u, 65536u, smb + MB_FQ);
        MBEX(smb + MB_FKH0, 32768u);
        bulkcp(smb + SM_KHI0, g_khi + (size_t)(b*32)*32768u, 32768u, smb + MB_FKH0);
    }

    const uint32_t qhiR = smb + SM_QHI + (uint32_t)(16*w + (g&1)*8 + lr)*512u;
    const uint32_t qloR = qhiR + (SM_QLO - SM_QHI);
    const uint32_t kr1  = (uint32_t)((g>>1)*8 + lr)*512u;   // GEMM1 B rows
    const uint32_t kr2  = (uint32_t)((g&1)*8 + lr)*512u;    // GEMM2 B rows

    float mA = -1e30f, mB = -1e30f, psA = 0.f, psB = 0.f;
    float acc[32][4];
    #pragma unroll
    for (int j = 0; j < 32; j++){ acc[j][0]=0.f; acc[j][1]=0.f; acc[j][2]=0.f; acc[j][3]=0.f; }

    MBW(smb + MB_FQ, 0);    // Q resident

    #pragma unroll 1
    for (int it = 0; it < NIT; it++){
        if (tid == 0 && it + 1 < NIT){
            int n = it + 1;
            uint32_t fb = (n & 1) ? (smb + MB_FKH1) : (smb + MB_FKH0);
            uint32_t eb = (n & 1) ? (smb + MB_EKH1) : (smb + MB_EKH0);
            if (n >= 2) MBW(eb, ((n - 2) >> 1) & 1);
            MBEX(fb, 32768u);
            bulkcp(smb + ((n & 1) ? SM_KHI1 : SM_KHI0),
                   g_khi + (size_t)(b*32 + n)*32768u, 32768u, fb);
        }
        MBW(smb + ((it & 1) ? MB_FKH1 : MB_FKH0), (it >> 1) & 1);

        const uint32_t kb = smb + ((it & 1) ? SM_KHI1 : SM_KHI0);

        // ---- GEMM1: S[16q x 64e] = Qhi*Khi + Qlo*Khi (log2 domain) --------
        float S[8][4];
        #pragma unroll
        for (int j = 0; j < 8; j++){ S[j][0]=0.f; S[j][1]=0.f; S[j][2]=0.f; S[j][3]=0.f; }

        #pragma unroll
        for (int c = 0; c < 16; c++){
            uint32_t qoff = (uint32_t)((((g>>1) + 2*c) ^ lr) << 4);
            uint32_t ah[4], al[4];
            ldsm4(ah, qhiR + qoff);
            ldsm4(al, qloR + qoff);
            uint32_t koff = (uint32_t)((((g&1) + 2*c) ^ lr) << 4);
            uint32_t bh[4][4];
            #pragma unroll
            for (int p = 0; p < 4; p++){
                uint32_t rof = kr1 + (uint32_t)p*8192u;
                ldsm4(bh[p], kb + rof + koff);
            }
            #pragma unroll
            for (int p = 0; p < 4; p++){ mma16816(S[2*p], ah, bh[p]); mma16816(S[2*p+1], ah, bh[p]+2); }
            #pragma unroll
            for (int p = 0; p < 4; p++){ mma16816(S[2*p], al, bh[p]); mma16816(S[2*p+1], al, bh[p]+2); }
        }

        // ---- online softmax, log2 domain (rows rA=16w+(lane>>2), rB=rA+8) -
        float bmA = -1e30f, bmB = -1e30f;
        #pragma unroll
        for (int j = 0; j < 8; j++){
            bmA = fmaxf(bmA, fmaxf(S[j][0], S[j][1]));
            bmB = fmaxf(bmB, fmaxf(S[j][2], S[j][3]));
        }
        bmA = fmaxf(bmA, __shfl_xor_sync(0xffffffffu, bmA, 1));
        bmA = fmaxf(bmA, __shfl_xor_sync(0xffffffffu, bmA, 2));
        bmB = fmaxf(bmB, __shfl_xor_sync(0xffffffffu, bmB, 1));
        bmB = fmaxf(bmB, __shfl_xor_sync(0xffffffffu, bmB, 2));

        float mnA = fmaxf(mA, bmA), mnB = fmaxf(mB, bmB);
        float alphaA = ex2f(mA - mnA), alphaB = ex2f(mB - mnB);
        mA = mnA; mB = mnB;

        uint32_t ph[8][2];
        float sA = 0.f, sB = 0.f;
        #pragma unroll
        for (int j = 0; j < 8; j++){
            __half2 dA = __floats2half2_rn(S[j][0] - mnA, S[j][1] - mnA);
            __half2 dB = __floats2half2_rn(S[j][2] - mnB, S[j][3] - mnB);
            uint32_t pA = h2ex2(*(uint32_t*)&dA);       // packed f16 P, 1 MUFU / 2 vals
            uint32_t pB = h2ex2(*(uint32_t*)&dB);
            float2 fA = __half22float2(*(__half2*)&pA);
            float2 fB = __half22float2(*(__half2*)&pB);
            sA += fA.x + fA.y;  sB += fB.x + fB.y;      // sum exactly what GEMM2 sees
            ph[j][0] = pA;
            ph[j][1] = pB;
        }
        psA = psA * alphaA + sA;      // per-thread partial row sums;
        psB = psB * alphaB + sB;      // cross-lane reduce deferred to epilogue

        if (!__all_sync(0xffffffffu, (alphaA == 1.f) & (alphaB == 1.f))){
            #pragma unroll
            for (int j = 0; j < 32; j++){
                acc[j][0] *= alphaA; acc[j][1] *= alphaA;
                acc[j][2] *= alphaB; acc[j][3] *= alphaB;
            }
        }

        // ---- GEMM2: acc[16q x 256d] += P[16q x 64e] * Khi[64e x 256d] -----
        #pragma unroll
        for (int kc = 0; kc < 4; kc++){
            uint32_t a[4] = { ph[2*kc][0], ph[2*kc][1], ph[2*kc+1][0], ph[2*kc+1][1] };
            uint32_t rof = kr2 + (uint32_t)kc*8192u;
            #pragma unroll
            for (int jj = 0; jj < 32; jj += 2){
                uint32_t bb[4];
                ldsm4t(bb, kb + rof + (uint32_t)((((g>>1) + jj) ^ lr) << 4));
                mma16816(acc[jj],   a, bb);
                mma16816(acc[jj+1], a, bb+2);
            }
        }
        if (lane == 0) MBARR(smb + ((it & 1) ? MB_EKH1 : MB_EKH0));  // done with Khi(it)
    }

    // ---- epilogue: reduce l across the 4 lanes of each row, write context --
    {
        float lA = psA, lB = psB;
        lA += __shfl_xor_sync(0xffffffffu, lA, 1);
        lA += __shfl_xor_sync(0xffffffffu, lA, 2);
        lB += __shfl_xor_sync(0xffffffffu, lB, 1);
        lB += __shfl_xor_sync(0xffffffffu, lB, 2);
        int rA = 16*w + (lane >> 2);
        float ivA = 1.f / lA, ivB = 1.f / lB;
        float* oA = out + ((size_t)(b*T_ + t0 + rA))    *(size_t)(2*D_) + D_ + (lane&3)*2;
        float* oB = out + ((size_t)(b*T_ + t0 + rA + 8))*(size_t)(2*D_) + D_ + (lane&3)*2;
        #pragma unroll
        for (int j = 0; j < 32; j++){
            *(float2*)(oA + 8*j) = make_float2(acc[j][0]*ivA, acc[j][1]*ivA);
            *(float2*)(oB + 8*j) = make_float2(acc[j][2]*ivB, acc[j][3]*ivB);
        }
    }
}

extern "C" void kernel_launch(void* const* d_in, const int* in_sizes, int n_in,
                              void* d_out, int out_size)
{
    const float* enc = (const float*)d_in[0];  // encoder_outputs [8,2048,256]
    const float* dec = (const float*)d_in[1];  // decoder_outputs [8,2048,256]
    float* out = (float*)d_out;                // [8,2048,512]
    (void)in_sizes; (void)n_in; (void)out_size;

    const int quads2 = 2 * B_*T_*D_/4;         // dec + enc quads
    pk_all<<<quads2/NTH, NTH>>>(dec, enc, out);

    cudaFuncSetAttribute(attn_main, cudaFuncAttributeMaxDynamicSharedMemorySize, SM_TOT);
    dim3 grid(T_/BQ, B_);                      // (16, 8) = 128 CTAs, single wave
    attn_main<<<grid, NTH, SM_TOT>>>(out);
}